// round 1
// baseline (speedup 1.0000x reference)
#include <cuda_runtime.h>

#define NUM_EMBED 8192
#define ED 64
#define NTOK 32768
#define HW 4096
#define CH_STRIDE 4096
#define B_STRIDE 262144
#define KB 256

// z_q: 8*64*64*64 = 2097152, loss: 1, idx: 32768, bincount: 8192
#define OFF_LOSS 2097152
#define OFF_IDX  2097153
#define OFF_BIN  (2097153 + 32768)

__device__ float g_cnormT[ED * NUM_EMBED];  // [c][k] transposed normalized codebook
__device__ int   g_idx[NTOK];
__device__ float g_partial[128];

typedef unsigned long long ull;

__device__ __forceinline__ void ffma2(ull &d, ull a, ull b) {
    asm("fma.rn.f32x2 %0, %1, %2, %0;" : "+l"(d) : "l"(a), "l"(b));
}
__device__ __forceinline__ float lo32(ull v) { return __uint_as_float((unsigned)(v & 0xFFFFFFFFULL)); }
__device__ __forceinline__ float hi32(ull v) { return __uint_as_float((unsigned)(v >> 32)); }

// ---------------- K1: normalize codebook, store transposed [c][k] ----------------
__global__ void k1_normalize(const float* __restrict__ ew) {
    int k = blockIdx.x * blockDim.x + threadIdx.x;
    if (k >= NUM_EMBED) return;
    const float4* row = (const float4*)(ew + (size_t)k * ED);
    float4 v[16];
    float ss = 0.f;
#pragma unroll
    for (int i = 0; i < 16; ++i) {
        v[i] = row[i];
        ss = fmaf(v[i].x, v[i].x, ss);
        ss = fmaf(v[i].y, v[i].y, ss);
        ss = fmaf(v[i].z, v[i].z, ss);
        ss = fmaf(v[i].w, v[i].w, ss);
    }
    float dn = fmaxf(__fsqrt_rn(ss), 1e-12f);
#pragma unroll
    for (int i = 0; i < 16; ++i) {
        g_cnormT[(4 * i + 0) * NUM_EMBED + k] = __fdiv_rn(v[i].x, dn);
        g_cnormT[(4 * i + 1) * NUM_EMBED + k] = __fdiv_rn(v[i].y, dn);
        g_cnormT[(4 * i + 2) * NUM_EMBED + k] = __fdiv_rn(v[i].z, dn);
        g_cnormT[(4 * i + 3) * NUM_EMBED + k] = __fdiv_rn(v[i].w, dn);
    }
}

// ---------------- K2: fused normalize-z + GEMM + argmax + bincount ----------------
// block: 64 tokens, 8 warps; warp w owns tokens [w*8, w*8+8); lane owns 8 codes/tile.
// smem: zs2 [c:64][t:64] f32x2 (z,z) duplicated & normalized (32KB)
//       ws  [c:64][k:256] float (64KB), nm[64]
#define SMEM_K2 (64*64*8 + 64*KB*4 + 64*4)

__global__ __launch_bounds__(256, 2) void k2_argmax(const float* __restrict__ z,
                                                    float* __restrict__ out_idx_f,
                                                    float* __restrict__ out_bin) {
    extern __shared__ char sm_[];
    float2* zs2 = (float2*)sm_;                              // 64*64 f32x2
    float*  ws  = (float*)(sm_ + 64 * 64 * 8);               // 64*256 float
    float*  nm  = (float*)(sm_ + 64 * 64 * 8 + 64 * KB * 4); // 64 float

    const int tid  = threadIdx.x;
    const int warp = tid >> 5;
    const int lane = tid & 31;

    const int tok0 = blockIdx.x * 64;
    const int b    = tok0 >> 12;
    const int p0   = tok0 & 4095;
    const float* zb = z + (size_t)b * B_STRIDE + p0;

    // load z tile (global is [c][token-contig]) and duplicate into f32x2 pairs
    for (int q = tid; q < 64 * 16; q += 256) {
        int c = q >> 4, t4 = q & 15;
        float4 v = ((const float4*)(zb + c * CH_STRIDE))[t4];
        float4* dst = (float4*)(zs2 + c * 64 + t4 * 4);
        dst[0] = make_float4(v.x, v.x, v.y, v.y);
        dst[1] = make_float4(v.z, v.z, v.w, v.w);
    }
    __syncthreads();

    // per-token norms
    if (tid < 64) {
        float ss = 0.f;
        for (int c = 0; c < 64; ++c) {
            float x = zs2[c * 64 + tid].x;
            ss = fmaf(x, x, ss);
        }
        nm[tid] = fmaxf(__fsqrt_rn(ss), 1e-12f);
    }
    __syncthreads();

    // normalize in place (division to match F.normalize rounding)
    for (int q = tid; q < 64 * 64; q += 256) {
        int t = q & 63;
        float x = __fdiv_rn(zs2[q].x, nm[t]);
        zs2[q] = make_float2(x, x);
    }
    __syncthreads();

    float best[8];
    int   bidx[8];
#pragma unroll
    for (int t = 0; t < 8; ++t) { best[t] = -1e30f; bidx[t] = 0; }

    const int t0 = warp * 8;

    for (int kt = 0; kt < NUM_EMBED; kt += KB) {
        // load code tile [c][k] (coalesced global, contiguous smem stores)
        for (int q = tid; q < 64 * (KB / 4); q += 256) {
            int c = q >> 6, k4 = q & 63;
            ((float4*)(ws + c * KB))[k4] =
                ((const float4*)(g_cnormT + c * NUM_EMBED + kt))[k4];
        }
        __syncthreads();

        ull acc[8][4];
#pragma unroll
        for (int t = 0; t < 8; ++t)
#pragma unroll
            for (int p = 0; p < 4; ++p) acc[t][p] = 0ULL;

#pragma unroll 8
        for (int c = 0; c < 64; ++c) {
            const ull* zp = (const ull*)zs2 + (c << 6) + t0;
            ulonglong2 a0 = *(const ulonglong2*)(zp + 0);
            ulonglong2 a1 = *(const ulonglong2*)(zp + 2);
            ulonglong2 a2 = *(const ulonglong2*)(zp + 4);
            ulonglong2 a3 = *(const ulonglong2*)(zp + 6);
            const ulonglong2* wp = (const ulonglong2*)(ws + c * KB + (lane << 3));
            ulonglong2 b0 = wp[0];
            ulonglong2 b1 = wp[1];
            ull aa[8] = {a0.x, a0.y, a1.x, a1.y, a2.x, a2.y, a3.x, a3.y};
            ull bb[4] = {b0.x, b0.y, b1.x, b1.y};
#pragma unroll
            for (int t = 0; t < 8; ++t)
#pragma unroll
                for (int p = 0; p < 4; ++p) ffma2(acc[t][p], aa[t], bb[p]);
        }

        // running argmax update, codes ascending (first-index-wins via strict >)
#pragma unroll
        for (int p = 0; p < 4; ++p) {
            int kb = kt + (lane << 3) + 2 * p;
#pragma unroll
            for (int t = 0; t < 8; ++t) {
                float lo = lo32(acc[t][p]);
                float hi = hi32(acc[t][p]);
                if (lo > best[t]) { best[t] = lo; bidx[t] = kb; }
                if (hi > best[t]) { best[t] = hi; bidx[t] = kb + 1; }
            }
        }
        __syncthreads();
    }

    // merge across lanes: lexicographic max on (val, -idx) -> first max index
#pragma unroll
    for (int t = 0; t < 8; ++t) {
        float v = best[t];
        int   i = bidx[t];
#pragma unroll
        for (int off = 16; off > 0; off >>= 1) {
            float v2 = __shfl_xor_sync(0xffffffffu, v, off);
            int   i2 = __shfl_xor_sync(0xffffffffu, i, off);
            if (v2 > v || (v2 == v && i2 < i)) { v = v2; i = i2; }
        }
        if (lane == 0) {
            int tg = tok0 + t0 + t;
            g_idx[tg] = i;
            out_idx_f[tg] = (float)i;
            atomicAdd(&out_bin[i], 1.0f);
        }
    }
}

// ---------------- K3: gather z_q, STE output, loss partials ----------------
__global__ void k3_zq_loss(const float* __restrict__ z, const float* __restrict__ ew,
                           float* __restrict__ out_zq) {
    int tg = blockIdx.x * 256 + threadIdx.x;
    int b = tg >> 12, p = tg & 4095;
    const float* zb = z + (size_t)b * B_STRIDE + p;
    float* ob = out_zq + (size_t)b * B_STRIDE + p;
    int idx = g_idx[tg];
    const float* w = ew + (size_t)idx * ED;
    float ss = 0.f;
#pragma unroll 8
    for (int c = 0; c < 64; ++c) {
        float zq = w[c];
        float zc = zb[c * CH_STRIDE];
        float d  = zq - zc;
        ob[c * CH_STRIDE] = zc + d;   // replicate STE arithmetic exactly
        ss = fmaf(d, d, ss);
    }
    __shared__ float red[256];
    red[threadIdx.x] = ss;
    __syncthreads();
    for (int s = 128; s > 0; s >>= 1) {
        if (threadIdx.x < s) red[threadIdx.x] += red[threadIdx.x + s];
        __syncthreads();
    }
    if (threadIdx.x == 0) g_partial[blockIdx.x] = red[0];
}

// ---------------- K4: deterministic loss finalize ----------------
__global__ void k4_loss(float* __restrict__ out_loss) {
    if (threadIdx.x == 0) {
        float s = 0.f;
        for (int i = 0; i < 128; ++i) s += g_partial[i];
        float m = s / 2097152.0f;
        out_loss[0] = 0.25f * m + m;  // beta*mean + mean, beta=0.25
    }
}

extern "C" void kernel_launch(void* const* d_in, const int* in_sizes, int n_in,
                              void* d_out, int out_size) {
    const float* z  = (const float*)d_in[0];
    const float* ew = (const float*)d_in[1];
    float* out      = (float*)d_out;

    float* out_zq   = out;
    float* out_loss = out + OFF_LOSS;
    float* out_idx  = out + OFF_IDX;
    float* out_bin  = out + OFF_BIN;

    cudaMemsetAsync(out_bin, 0, NUM_EMBED * sizeof(float));

    k1_normalize<<<NUM_EMBED / 256, 256>>>(ew);

    cudaFuncSetAttribute(k2_argmax, cudaFuncAttributeMaxDynamicSharedMemorySize, SMEM_K2);
    k2_argmax<<<NTOK / 64, 256, SMEM_K2>>>(z, out_idx, out_bin);

    k3_zq_loss<<<NTOK / 256, 256>>>(z, ew, out_zq);
    k4_loss<<<1, 32>>>(out_loss);
}